// round 9
// baseline (speedup 1.0000x reference)
#include <cuda_runtime.h>
#include <cuda_fp16.h>
#include <cuda_bf16.h>

// FFT-based 2x upsample, fully-real polyphase formulation (see R2/R3/R5).
// R9 = R8 + twiddle-power TABLES: every twapply chain (7-deep serial cmul,
// 6 cmul extra per stage) is replaced by exact per-(k,tid) table lookups;
// inverse stages multiply by the conjugate entry (cmulc, same cost).
// Kills ~22% of FMA instructions and ALL serial twiddle chains.

#define FN    4096
#define TPB   512
#define NPAIR (FN / 2)
#define SMEM_FFT (2 * FN * sizeof(float2))   // 64 KB double-buffer

__device__ __align__(16) __half2 g_B [(size_t)FN * FN];  // (x, R_row)
__device__ __align__(16) __half2 g_Bt[(size_t)FN * FN];  // B transposed
__device__ __align__(16) __half2 g_R [(size_t)FN * FN];  // (Ru, Rv') per (c,i)
__device__ float g_Dpart[NPAIR];
__device__ float g_D[1];
// Twiddle power tables (exact):
//  P1[(k-1)*512+t] = e^{-2pi i k t/4096},  k=1..7, t<512
//  P2[(k-1)*64+s]  = e^{-2pi i k s/512},   k=1..7, s<64   (8s/4096 = s/512)
//  P3[(k-1)*8+n]   = e^{-2pi i k n/64},    k=1..7, n<8
//  PH[j*512+m]     = e^{+i pi (m+512j)/4096} * (j>=4 ? -1 : +1)
__device__ __align__(16) float2 g_P1[7 * 512];
__device__ __align__(16) float2 g_P2[7 * 64];
__device__ __align__(16) float2 g_P3[7 * 8];
__device__ __align__(16) float2 g_PH[8 * 512];

__device__ __forceinline__ float2 cmul(float2 a, float2 b) {
    return make_float2(fmaf(a.x, b.x, -a.y * b.y), fmaf(a.x, b.y, a.y * b.x));
}
// a * conj(b)
__device__ __forceinline__ float2 cmulc(float2 a, float2 b) {
    return make_float2(fmaf(a.x, b.x, a.y * b.y), fmaf(a.y, b.x, -a.x * b.y));
}
__device__ __forceinline__ float2 cadd(float2 a, float2 b) { return make_float2(a.x + b.x, a.y + b.y); }
__device__ __forceinline__ float2 csub(float2 a, float2 b) { return make_float2(a.x - b.x, a.y - b.y); }

__global__ void k0_twiddle() {
    int t = threadIdx.x;      // 0..511
    float sn, cs;
    #pragma unroll
    for (int k = 1; k < 8; k++) {
        sincospif(-2.0f * (float)(k * t) / 4096.0f, &sn, &cs);
        g_P1[(k - 1) * 512 + t] = make_float2(cs, sn);
    }
    if (t < 64) {
        #pragma unroll
        for (int k = 1; k < 8; k++) {
            sincospif(-2.0f * (float)(k * t) / 512.0f, &sn, &cs);
            g_P2[(k - 1) * 64 + t] = make_float2(cs, sn);
        }
    }
    if (t < 8) {
        #pragma unroll
        for (int k = 1; k < 8; k++) {
            sincospif(-2.0f * (float)(k * t) / 64.0f, &sn, &cs);
            g_P3[(k - 1) * 8 + t] = make_float2(cs, sn);
        }
    }
    #pragma unroll
    for (int j = 0; j < 8; j++) {
        sincospif((float)(t + 512 * j) / 4096.0f, &sn, &cs);
        float sg = (j >= 4) ? -1.0f : 1.0f;
        g_PH[j * 512 + t] = make_float2(sg * cs, sg * sn);
    }
}

// Radix-8 DFT butterfly. FWD: W_8 = e^{-2pi i/8}; INV: conjugate.
template <bool INV>
__device__ __forceinline__ void bfly8(const float2 x[8], float2 y[8]) {
    float2 a0 = cadd(x[0], x[4]), a1 = csub(x[0], x[4]);
    float2 a2 = cadd(x[2], x[6]), a3 = csub(x[2], x[6]);
    float2 a4 = cadd(x[1], x[5]), a5 = csub(x[1], x[5]);
    float2 a6 = cadd(x[3], x[7]), a7 = csub(x[3], x[7]);
    float2 b0 = cadd(a0, a2), b1 = csub(a0, a2);
    float2 b2 = cadd(a4, a6), b3 = csub(a4, a6);
    float2 c3  = INV ? make_float2(-a3.y, a3.x) : make_float2(a3.y, -a3.x);
    float2 c7  = INV ? make_float2(-a7.y, a7.x) : make_float2(a7.y, -a7.x);
    float2 jb3 = INV ? make_float2(-b3.y, b3.x) : make_float2(b3.y, -b3.x);
    float2 e1 = cadd(a1, c3), e3 = csub(a1, c3);
    float2 f5 = cadd(a5, c7), f7 = csub(a5, c7);
    const float s = 0.70710678118654752440f;
    float2 W1 = INV ? make_float2(s, s)  : make_float2(s, -s);
    float2 W3 = INV ? make_float2(-s, s) : make_float2(-s, -s);
    float2 g5 = cmul(W1, f5), g7 = cmul(W3, f7);
    y[0] = cadd(b0, b2); y[4] = csub(b0, b2);
    y[2] = cadd(b1, jb3); y[6] = csub(b1, jb3);
    y[1] = cadd(e1, g5); y[5] = csub(e1, g5);
    y[3] = cadd(e3, g7); y[7] = csub(e3, g7);
}

// Multiply y[1..7] by table powers (FWD) or their conjugates (INV).
template <bool INV>
__device__ __forceinline__ void twtab(float2 y[8], const float2* __restrict__ tab,
                                      int stride, int idx) {
    #pragma unroll
    for (int k = 1; k < 8; k++) {
        float2 w = __ldg(&tab[(k - 1) * stride + idx]);
        y[k] = INV ? cmulc(y[k], w) : cmul(y[k], w);
    }
}

// S-transform: z <- N * IDFT( DFT(z) * halfshift_w ), zny <- DFT(z)[2048].
// Exchange addressing identical to R8 (factored GF(2)-linear swizzle).
__device__ __forceinline__ void stransform(float2 z[8], float2* buf0, float2* buf1,
                                           float2* s_zny, int tid, float2* zny_out) {
    const int k0 = tid >> 6;
    const int s6 = tid & 63;
    const int k1 = (tid >> 3) & 7;
    const int n0 = tid & 7;
    const int m  = k0 + 8 * k1 + 64 * n0;

    const int swtid = tid ^ ((tid >> 2) & 4) ^ ((tid >> 4) & 2) ^ (((tid >> 6) & 1) * 9);
    const int b2    = 512 * k0 + (s6 ^ ((s6 >> 2) & 4) ^ ((s6 >> 4) & 2));
    const int b2x   = b2 ^ 9;
    const int b3a   = 512 * k0 + 64 * k1 + n0;
    const int m9    = (k1 & 1) * 9;
    const int M0 = m9, M1 = m9 ^ 4, M2 = m9 ^ 2, M3 = m9 ^ 6;
    const int b4    = (8 * tid) ^ (((tid & 2) << 1) ^ ((tid & 4) >> 1) ^ ((tid & 8) ? 9 : 0));

    float2 y[8], t[8];

    // ---- forward FFT ----
    bfly8<false>(z, y);
    twtab<false>(y, g_P1, 512, tid);
    #pragma unroll
    for (int q = 0; q < 8; q++) buf0[swtid + 512 * q] = y[q];
    __syncthreads();
    #pragma unroll
    for (int q = 0; q < 8; q++) t[q] = buf0[((q & 1) ? b2x : b2) + 64 * q];

    bfly8<false>(t, y);
    twtab<false>(y, g_P2, 64, s6);
    #pragma unroll
    for (int q = 0; q < 8; q++) buf1[((q & 1) ? b2x : b2) + 64 * q] = y[q];
    __syncthreads();
    {
        t[0] = buf1[(b3a +  0) ^ M0]; t[1] = buf1[(b3a +  8) ^ M0];
        t[2] = buf1[(b3a + 16) ^ M1]; t[3] = buf1[(b3a + 24) ^ M1];
        t[4] = buf1[(b3a + 32) ^ M2]; t[5] = buf1[(b3a + 40) ^ M2];
        t[6] = buf1[(b3a + 48) ^ M3]; t[7] = buf1[(b3a + 56) ^ M3];
    }

    bfly8<false>(t, y);
    twtab<false>(y, g_P3, 8, n0);
    {
        buf0[(b3a +  0) ^ M0] = y[0]; buf0[(b3a +  8) ^ M0] = y[1];
        buf0[(b3a + 16) ^ M1] = y[2]; buf0[(b3a + 24) ^ M1] = y[3];
        buf0[(b3a + 32) ^ M2] = y[4]; buf0[(b3a + 40) ^ M2] = y[5];
        buf0[(b3a + 48) ^ M3] = y[6]; buf0[(b3a + 56) ^ M3] = y[7];
    }
    __syncthreads();
    #pragma unroll
    for (int q = 0; q < 8; q++) t[q] = buf0[b4 ^ q];

    bfly8<false>(t, y);                         // -> X[m + 512 j]
    if (tid == 0) *s_zny = y[4];                // zny = X[2048]

    // ---- half-sample-shift phase: y[j] *= PH[j][m] (fused wm*EJ, exact) ----
    #pragma unroll
    for (int j = 0; j < 8; j++) y[j] = cmul(y[j], __ldg(&g_PH[j * 512 + m]));

    // ---- inverse FFT ----
    bfly8<true>(y, t);
    #pragma unroll
    for (int q = 0; q < 8; q++) buf1[b4 ^ q] = t[q];
    __syncthreads();
    {
        t[0] = buf1[(b3a +  0) ^ M0]; t[1] = buf1[(b3a +  8) ^ M0];
        t[2] = buf1[(b3a + 16) ^ M1]; t[3] = buf1[(b3a + 24) ^ M1];
        t[4] = buf1[(b3a + 32) ^ M2]; t[5] = buf1[(b3a + 40) ^ M2];
        t[6] = buf1[(b3a + 48) ^ M3]; t[7] = buf1[(b3a + 56) ^ M3];
    }

    twtab<true>(t, g_P3, 8, n0);
    bfly8<true>(t, y);
    {
        buf0[(b3a +  0) ^ M0] = y[0]; buf0[(b3a +  8) ^ M0] = y[1];
        buf0[(b3a + 16) ^ M1] = y[2]; buf0[(b3a + 24) ^ M1] = y[3];
        buf0[(b3a + 32) ^ M2] = y[4]; buf0[(b3a + 40) ^ M2] = y[5];
        buf0[(b3a + 48) ^ M3] = y[6]; buf0[(b3a + 56) ^ M3] = y[7];
    }
    __syncthreads();
    #pragma unroll
    for (int q = 0; q < 8; q++) t[q] = buf0[((q & 1) ? b2x : b2) + 64 * q];

    twtab<true>(t, g_P2, 64, s6);
    bfly8<true>(t, y);
    #pragma unroll
    for (int q = 0; q < 8; q++) buf1[((q & 1) ? b2x : b2) + 64 * q] = y[q];
    __syncthreads();
    #pragma unroll
    for (int q = 0; q < 8; q++) t[q] = buf1[swtid + 512 * q];

    twtab<true>(t, g_P1, 512, tid);
    bfly8<true>(t, z);                          // z[n3] = N*S[tid+512 n3]

    *zny_out = *s_zny;                          // >= 3 syncs after the write
}

// K1: 2-for-1 row pass (block r handles input rows 2r, 2r+1).
__global__ __launch_bounds__(TPB) void k1_rowpass(const float* __restrict__ x) {
    extern __shared__ float2 dsm[];
    __shared__ float2 s_zny;
    float2* buf0 = dsm;
    float2* buf1 = dsm + FN;
    int tid = threadIdx.x;
    size_t r = blockIdx.x;
    const float* u = x + (2 * r) * (size_t)FN;
    const float* v = u + FN;
    float2 z[8], z0[8];
    #pragma unroll
    for (int e = 0; e < 8; e++) {
        int j = tid + e * TPB;
        z[e] = make_float2(u[j], v[j]);
        z0[e] = z[e];
    }
    float2 zny;
    stransform(z, buf0, buf1, &s_zny, tid, &zny);
    if (tid == 0) g_Dpart[r] = zny.x - zny.y;

    const float invN = 1.0f / 4096.0f;
    float sgn = (tid & 1) ? -1.0f : 1.0f;       // (-1)^j
    __half2* row0 = g_B + (2 * r) * (size_t)FN;
    __half2* row1 = row0 + FN;
    #pragma unroll
    for (int e = 0; e < 8; e++) {
        int j = tid + e * TPB;
        float Ru = (z[e].x - sgn * zny.y) * invN;
        float Rv = (z[e].y + sgn * zny.x) * invN;
        row0[j] = __floats2half2_rn(z0[e].x, Ru);
        row1[j] = __floats2half2_rn(z0[e].y, Rv);
    }
}

// Deterministic reduction of g_Dpart -> g_D.
__global__ void k_reduce() {
    __shared__ float sh[TPB];
    float s = 0.0f;
    for (int i = threadIdx.x; i < NPAIR; i += TPB) s += g_Dpart[i];
    sh[threadIdx.x] = s;
    __syncthreads();
    for (int o = TPB / 2; o > 0; o >>= 1) {
        if (threadIdx.x < o) sh[threadIdx.x] += sh[threadIdx.x + o];
        __syncthreads();
    }
    if (threadIdx.x == 0) g_D[0] = sh[0];
}

// K2: transpose B [4096x4096 half2] -> Bt.
__global__ void k2_transpose() {
    __shared__ __half2 tile[32][33];
    int tx = threadIdx.x, ty = threadIdx.y;
    int cx = blockIdx.x * 32 + tx;
    int ry = blockIdx.y * 32 + ty;
    #pragma unroll
    for (int j = 0; j < 32; j += 8)
        tile[ty + j][tx] = g_B[(size_t)(ry + j) * FN + cx];
    __syncthreads();
    int ox = blockIdx.y * 32 + tx;
    int oy = blockIdx.x * 32 + ty;
    #pragma unroll
    for (int j = 0; j < 32; j += 8)
        g_Bt[(size_t)(oy + j) * FN + ox] = tile[tx][ty + j];
}

// K3: 2-for-1 column pass (block c handles output columns 2c, 2c+1).
// Writes ONLY the odd-row values: R[c][i] = (Ru, Rv + parity corr).
__global__ __launch_bounds__(TPB) void k3_colpass() {
    extern __shared__ float2 dsm[];
    __shared__ float2 s_zny;
    float2* buf0 = dsm;
    float2* buf1 = dsm + FN;
    int tid = threadIdx.x;
    size_t c = blockIdx.x;
    const __half2* bt = g_Bt + c * (size_t)FN;
    float2 z[8];
    #pragma unroll
    for (int e = 0; e < 8; e++) {
        int j = tid + e * TPB;
        z[e] = __half22float2(bt[j]);
    }
    float2 zny;
    stransform(z, buf0, buf1, &s_zny, tid, &zny);

    const float invN = 1.0f / 4096.0f;
    float corr = -g_D[0] * invN * invN;         // -D/N^2
    float sgnc = (c & 1) ? -corr : corr;        // (-1)^c * corr
    float sgn = (tid & 1) ? -1.0f : 1.0f;       // (-1)^i
    __half2* rr = g_R + c * (size_t)FN;
    #pragma unroll
    for (int e = 0; e < 8; e++) {
        int j = tid + e * TPB;
        float Ru = (z[e].x - sgn * zny.y) * invN;
        float Rv = (z[e].y + sgn * zny.x) * invN;
        rr[j] = __floats2half2_rn(Ru, Rv + sgn * sgnc);
    }
}

// K4: assemble output from Bt + R; 64-wide c tiles, float4 stores.
//   out[2i  ][2c..2c+1] = Bt[c][i]   out[2i+1][2c..2c+1] = R[c][i]
__global__ void k4_assemble(float* __restrict__ out) {
    __shared__ __half2 tB[32][66];   // [i_loc][c_loc], +2 pad
    __shared__ __half2 tR[32][66];
    int tx = threadIdx.x, ty = threadIdx.y;    // 32 x 8
    int ib = blockIdx.x * 32;                  // i tile (32)
    int cb = blockIdx.y * 64;                  // c tile (64)
    #pragma unroll
    for (int j = 0; j < 64; j += 8) {
        int c_loc = ty + j;
        tB[tx][c_loc] = g_Bt[(size_t)(cb + c_loc) * FN + ib + tx];
        tR[tx][c_loc] = g_R [(size_t)(cb + c_loc) * FN + ib + tx];
    }
    __syncthreads();
    float4* o4 = reinterpret_cast<float4*>(out);   // row stride 2048 float4
    int cq = (cb >> 1) + tx;                       // float4 col index
    #pragma unroll
    for (int j = 0; j < 32; j += 8) {
        int i_loc = ty + j;
        size_t ig = (size_t)(ib + i_loc);
        float2 a0 = __half22float2(tB[i_loc][2 * tx]);
        float2 a1 = __half22float2(tB[i_loc][2 * tx + 1]);
        o4[(2 * ig) * 2048 + cq] = make_float4(a0.x, a0.y, a1.x, a1.y);
        float2 b0 = __half22float2(tR[i_loc][2 * tx]);
        float2 b1 = __half22float2(tR[i_loc][2 * tx + 1]);
        o4[(2 * ig + 1) * 2048 + cq] = make_float4(b0.x, b0.y, b1.x, b1.y);
    }
}

extern "C" void kernel_launch(void* const* d_in, const int* in_sizes, int n_in,
                              void* d_out, int out_size) {
    const float* x = (const float*)d_in[0];
    float* out = (float*)d_out;
    (void)in_sizes; (void)n_in; (void)out_size;

    cudaFuncSetAttribute(k1_rowpass, cudaFuncAttributeMaxDynamicSharedMemorySize,
                         (int)SMEM_FFT);
    cudaFuncSetAttribute(k3_colpass, cudaFuncAttributeMaxDynamicSharedMemorySize,
                         (int)SMEM_FFT);

    k0_twiddle<<<1, 512>>>();
    k1_rowpass<<<NPAIR, TPB, SMEM_FFT>>>(x);
    k_reduce<<<1, TPB>>>();
    k2_transpose<<<dim3(FN / 32, FN / 32), dim3(32, 8)>>>();
    k3_colpass<<<FN, TPB, SMEM_FFT>>>();
    k4_assemble<<<dim3(FN / 32, FN / 64), dim3(32, 8)>>>(out);
}

// round 10
// speedup vs baseline: 1.3709x; 1.3709x over previous
#include <cuda_runtime.h>
#include <cuda_fp16.h>
#include <cuda_bf16.h>

// FFT-based 2x upsample, fully-real polyphase formulation (see R2/R3/R5).
// R10 = R8 (best, 225.3us) + packed-fp32 butterflies:
//   cadd/csub emit add/sub.rn.f32x2 (sm_100+ packed fp32, PTX ISA 8.6) —
//   one instruction per complex add/sub instead of two. Numerics identical.
//   twapply power chain is a depth-3 tree (same op count, half the depth).
// R9's global twiddle tables reverted (50 LDG/thread cost >> FMA savings).

#define FN    4096
#define TPB   512
#define NPAIR (FN / 2)
#define SMEM_FFT (2 * FN * sizeof(float2))   // 64 KB double-buffer

__device__ __align__(16) __half2 g_B [(size_t)FN * FN];  // (x, R_row)
__device__ __align__(16) __half2 g_Bt[(size_t)FN * FN];  // B transposed
__device__ __align__(16) __half2 g_R [(size_t)FN * FN];  // (Ru, Rv') per (c,i)
__device__ float g_Dpart[NPAIR];
__device__ float g_D[1];
// twA[k] = e^{-2 pi i k/4096}, twB[k] = e^{+i pi k/4096}, k < 512
__device__ __align__(16) float2 g_twA[512];
__device__ __align__(16) float2 g_twB[512];

__device__ __forceinline__ float2 cmul(float2 a, float2 b) {
    return make_float2(fmaf(a.x, b.x, -a.y * b.y), fmaf(a.x, b.y, a.y * b.x));
}
__device__ __forceinline__ float2 cconj(float2 a) { return make_float2(a.x, -a.y); }

// Packed fp32 complex add/sub: ONE f32x2 instruction each. The mov.b64
// pack/unpack pairs are eliminated by ptxas via aligned register pairs.
__device__ __forceinline__ float2 cadd(float2 a, float2 b) {
    float2 r;
    asm("{\n\t.reg .b64 ra, rb, rc;\n\t"
        "mov.b64 ra, {%2, %3};\n\t"
        "mov.b64 rb, {%4, %5};\n\t"
        "add.rn.f32x2 rc, ra, rb;\n\t"
        "mov.b64 {%0, %1}, rc;\n\t}"
        : "=f"(r.x), "=f"(r.y)
        : "f"(a.x), "f"(a.y), "f"(b.x), "f"(b.y));
    return r;
}
__device__ __forceinline__ float2 csub(float2 a, float2 b) {
    float2 r;
    asm("{\n\t.reg .b64 ra, rb, rc;\n\t"
        "mov.b64 ra, {%2, %3};\n\t"
        "mov.b64 rb, {%4, %5};\n\t"
        "sub.rn.f32x2 rc, ra, rb;\n\t"
        "mov.b64 {%0, %1}, rc;\n\t}"
        : "=f"(r.x), "=f"(r.y)
        : "f"(a.x), "f"(a.y), "f"(b.x), "f"(b.y));
    return r;
}

__global__ void k0_twiddle() {
    int k = threadIdx.x;
    float sn, cs;
    sincospif(-(float)k / 2048.0f, &sn, &cs);
    g_twA[k] = make_float2(cs, sn);
    sincospif((float)k / 4096.0f, &sn, &cs);
    g_twB[k] = make_float2(cs, sn);
}

// Radix-8 DFT butterfly. FWD: W_8 = e^{-2pi i/8}; INV: conjugate.
template <bool INV>
__device__ __forceinline__ void bfly8(const float2 x[8], float2 y[8]) {
    float2 a0 = cadd(x[0], x[4]), a1 = csub(x[0], x[4]);
    float2 a2 = cadd(x[2], x[6]), a3 = csub(x[2], x[6]);
    float2 a4 = cadd(x[1], x[5]), a5 = csub(x[1], x[5]);
    float2 a6 = cadd(x[3], x[7]), a7 = csub(x[3], x[7]);
    float2 b0 = cadd(a0, a2), b1 = csub(a0, a2);
    float2 b2 = cadd(a4, a6), b3 = csub(a4, a6);
    float2 c3  = INV ? make_float2(-a3.y, a3.x) : make_float2(a3.y, -a3.x);
    float2 c7  = INV ? make_float2(-a7.y, a7.x) : make_float2(a7.y, -a7.x);
    float2 jb3 = INV ? make_float2(-b3.y, b3.x) : make_float2(b3.y, -b3.x);
    float2 e1 = cadd(a1, c3), e3 = csub(a1, c3);
    float2 f5 = cadd(a5, c7), f7 = csub(a5, c7);
    const float s = 0.70710678118654752440f;
    float2 W1 = INV ? make_float2(s, s)  : make_float2(s, -s);
    float2 W3 = INV ? make_float2(-s, s) : make_float2(-s, -s);
    float2 g5 = cmul(W1, f5), g7 = cmul(W3, f7);
    y[0] = cadd(b0, b2); y[4] = csub(b0, b2);
    y[2] = cadd(b1, jb3); y[6] = csub(b1, jb3);
    y[1] = cadd(e1, g5); y[5] = csub(e1, g5);
    y[3] = cadd(e3, g7); y[7] = csub(e3, g7);
}

// y[k] *= w^k, k=1..7. Powers built as a depth-3 tree (not a serial chain).
__device__ __forceinline__ void twapply(float2 y[8], float2 w) {
    float2 w2 = cmul(w, w);
    float2 w3 = cmul(w2, w);
    float2 w4 = cmul(w2, w2);
    float2 w5 = cmul(w3, w2);
    float2 w6 = cmul(w3, w3);
    float2 w7 = cmul(w4, w3);
    y[1] = cmul(y[1], w);  y[2] = cmul(y[2], w2);
    y[3] = cmul(y[3], w3); y[4] = cmul(y[4], w4);
    y[5] = cmul(y[5], w5); y[6] = cmul(y[6], w6);
    y[7] = cmul(y[7], w7);
}

// S-transform: z <- N * IDFT( DFT(z) * halfshift_w ), zny <- DFT(z)[2048].
// Exchange addressing identical to R8 (factored GF(2)-linear swizzle).
__device__ __forceinline__ void stransform(float2 z[8], float2* buf0, float2* buf1,
                                           float2* s_zny, int tid, float2* zny_out) {
    const int k0 = tid >> 6;
    const int s6 = tid & 63;
    const int k1 = (tid >> 3) & 7;
    const int n0 = tid & 7;
    const int m  = k0 + 8 * k1 + 64 * n0;

    const int swtid = tid ^ ((tid >> 2) & 4) ^ ((tid >> 4) & 2) ^ (((tid >> 6) & 1) * 9);
    const int b2    = 512 * k0 + (s6 ^ ((s6 >> 2) & 4) ^ ((s6 >> 4) & 2));
    const int b2x   = b2 ^ 9;
    const int b3a   = 512 * k0 + 64 * k1 + n0;
    const int m9    = (k1 & 1) * 9;
    const int M0 = m9, M1 = m9 ^ 4, M2 = m9 ^ 2, M3 = m9 ^ 6;
    const int b4    = (8 * tid) ^ (((tid & 2) << 1) ^ ((tid & 4) >> 1) ^ ((tid & 8) ? 9 : 0));

    float2 y[8], t[8];

    const float2 w1b = __ldg(&g_twA[tid]);
    const float2 w2b = __ldg(&g_twA[8 * s6]);
    const float2 w3b = __ldg(&g_twA[64 * n0]);
    const float2 wm  = __ldg(&g_twB[m]);

    // ---- forward FFT ----
    bfly8<false>(z, y);
    twapply(y, w1b);
    #pragma unroll
    for (int q = 0; q < 8; q++) buf0[swtid + 512 * q] = y[q];
    __syncthreads();
    #pragma unroll
    for (int q = 0; q < 8; q++) t[q] = buf0[((q & 1) ? b2x : b2) + 64 * q];

    bfly8<false>(t, y);
    twapply(y, w2b);
    #pragma unroll
    for (int q = 0; q < 8; q++) buf1[((q & 1) ? b2x : b2) + 64 * q] = y[q];
    __syncthreads();
    {
        t[0] = buf1[(b3a +  0) ^ M0]; t[1] = buf1[(b3a +  8) ^ M0];
        t[2] = buf1[(b3a + 16) ^ M1]; t[3] = buf1[(b3a + 24) ^ M1];
        t[4] = buf1[(b3a + 32) ^ M2]; t[5] = buf1[(b3a + 40) ^ M2];
        t[6] = buf1[(b3a + 48) ^ M3]; t[7] = buf1[(b3a + 56) ^ M3];
    }

    bfly8<false>(t, y);
    twapply(y, w3b);
    {
        buf0[(b3a +  0) ^ M0] = y[0]; buf0[(b3a +  8) ^ M0] = y[1];
        buf0[(b3a + 16) ^ M1] = y[2]; buf0[(b3a + 24) ^ M1] = y[3];
        buf0[(b3a + 32) ^ M2] = y[4]; buf0[(b3a + 40) ^ M2] = y[5];
        buf0[(b3a + 48) ^ M3] = y[6]; buf0[(b3a + 56) ^ M3] = y[7];
    }
    __syncthreads();
    #pragma unroll
    for (int q = 0; q < 8; q++) t[q] = buf0[b4 ^ q];

    bfly8<false>(t, y);                         // -> X[m + 512 j]
    if (tid == 0) *s_zny = y[4];                // zny = X[2048]

    // ---- half-sample-shift phase (registers) ----
    {
        const float2 EJ[8] = {
            { 1.0f, 0.0f},
            { 0.92387953251128675613f,  0.38268343236508977173f},
            { 0.70710678118654752440f,  0.70710678118654752440f},
            { 0.38268343236508977173f,  0.92387953251128675613f},
            { 0.0f, -1.0f},
            { 0.38268343236508977173f, -0.92387953251128675613f},
            { 0.70710678118654752440f, -0.70710678118654752440f},
            { 0.92387953251128675613f, -0.38268343236508977173f}};
        #pragma unroll
        for (int j = 0; j < 8; j++) y[j] = cmul(y[j], cmul(wm, EJ[j]));
    }

    // ---- inverse FFT ----
    bfly8<true>(y, t);
    #pragma unroll
    for (int q = 0; q < 8; q++) buf1[b4 ^ q] = t[q];
    __syncthreads();
    {
        t[0] = buf1[(b3a +  0) ^ M0]; t[1] = buf1[(b3a +  8) ^ M0];
        t[2] = buf1[(b3a + 16) ^ M1]; t[3] = buf1[(b3a + 24) ^ M1];
        t[4] = buf1[(b3a + 32) ^ M2]; t[5] = buf1[(b3a + 40) ^ M2];
        t[6] = buf1[(b3a + 48) ^ M3]; t[7] = buf1[(b3a + 56) ^ M3];
    }

    twapply(t, cconj(w3b));
    bfly8<true>(t, y);
    {
        buf0[(b3a +  0) ^ M0] = y[0]; buf0[(b3a +  8) ^ M0] = y[1];
        buf0[(b3a + 16) ^ M1] = y[2]; buf0[(b3a + 24) ^ M1] = y[3];
        buf0[(b3a + 32) ^ M2] = y[4]; buf0[(b3a + 40) ^ M2] = y[5];
        buf0[(b3a + 48) ^ M3] = y[6]; buf0[(b3a + 56) ^ M3] = y[7];
    }
    __syncthreads();
    #pragma unroll
    for (int q = 0; q < 8; q++) t[q] = buf0[((q & 1) ? b2x : b2) + 64 * q];

    twapply(t, cconj(w2b));
    bfly8<true>(t, y);
    #pragma unroll
    for (int q = 0; q < 8; q++) buf1[((q & 1) ? b2x : b2) + 64 * q] = y[q];
    __syncthreads();
    #pragma unroll
    for (int q = 0; q < 8; q++) t[q] = buf1[swtid + 512 * q];

    twapply(t, cconj(w1b));
    bfly8<true>(t, z);                          // z[n3] = N*S[tid+512 n3]

    *zny_out = *s_zny;                          // >= 3 syncs after the write
}

// K1: 2-for-1 row pass (block r handles input rows 2r, 2r+1).
__global__ __launch_bounds__(TPB) void k1_rowpass(const float* __restrict__ x) {
    extern __shared__ float2 dsm[];
    __shared__ float2 s_zny;
    float2* buf0 = dsm;
    float2* buf1 = dsm + FN;
    int tid = threadIdx.x;
    size_t r = blockIdx.x;
    const float* u = x + (2 * r) * (size_t)FN;
    const float* v = u + FN;
    float2 z[8], z0[8];
    #pragma unroll
    for (int e = 0; e < 8; e++) {
        int j = tid + e * TPB;
        z[e] = make_float2(u[j], v[j]);
        z0[e] = z[e];
    }
    float2 zny;
    stransform(z, buf0, buf1, &s_zny, tid, &zny);
    if (tid == 0) g_Dpart[r] = zny.x - zny.y;

    const float invN = 1.0f / 4096.0f;
    float sgn = (tid & 1) ? -1.0f : 1.0f;       // (-1)^j
    __half2* row0 = g_B + (2 * r) * (size_t)FN;
    __half2* row1 = row0 + FN;
    #pragma unroll
    for (int e = 0; e < 8; e++) {
        int j = tid + e * TPB;
        float Ru = (z[e].x - sgn * zny.y) * invN;
        float Rv = (z[e].y + sgn * zny.x) * invN;
        row0[j] = __floats2half2_rn(z0[e].x, Ru);
        row1[j] = __floats2half2_rn(z0[e].y, Rv);
    }
}

// Deterministic reduction of g_Dpart -> g_D.
__global__ void k_reduce() {
    __shared__ float sh[TPB];
    float s = 0.0f;
    for (int i = threadIdx.x; i < NPAIR; i += TPB) s += g_Dpart[i];
    sh[threadIdx.x] = s;
    __syncthreads();
    for (int o = TPB / 2; o > 0; o >>= 1) {
        if (threadIdx.x < o) sh[threadIdx.x] += sh[threadIdx.x + o];
        __syncthreads();
    }
    if (threadIdx.x == 0) g_D[0] = sh[0];
}

// K2: transpose B [4096x4096 half2] -> Bt.
__global__ void k2_transpose() {
    __shared__ __half2 tile[32][33];
    int tx = threadIdx.x, ty = threadIdx.y;
    int cx = blockIdx.x * 32 + tx;
    int ry = blockIdx.y * 32 + ty;
    #pragma unroll
    for (int j = 0; j < 32; j += 8)
        tile[ty + j][tx] = g_B[(size_t)(ry + j) * FN + cx];
    __syncthreads();
    int ox = blockIdx.y * 32 + tx;
    int oy = blockIdx.x * 32 + ty;
    #pragma unroll
    for (int j = 0; j < 32; j += 8)
        g_Bt[(size_t)(oy + j) * FN + ox] = tile[tx][ty + j];
}

// K3: 2-for-1 column pass (block c handles output columns 2c, 2c+1).
// Writes ONLY the odd-row values: R[c][i] = (Ru, Rv + parity corr).
__global__ __launch_bounds__(TPB) void k3_colpass() {
    extern __shared__ float2 dsm[];
    __shared__ float2 s_zny;
    float2* buf0 = dsm;
    float2* buf1 = dsm + FN;
    int tid = threadIdx.x;
    size_t c = blockIdx.x;
    const __half2* bt = g_Bt + c * (size_t)FN;
    float2 z[8];
    #pragma unroll
    for (int e = 0; e < 8; e++) {
        int j = tid + e * TPB;
        z[e] = __half22float2(bt[j]);
    }
    float2 zny;
    stransform(z, buf0, buf1, &s_zny, tid, &zny);

    const float invN = 1.0f / 4096.0f;
    float corr = -g_D[0] * invN * invN;         // -D/N^2
    float sgnc = (c & 1) ? -corr : corr;        // (-1)^c * corr
    float sgn = (tid & 1) ? -1.0f : 1.0f;       // (-1)^i
    __half2* rr = g_R + c * (size_t)FN;
    #pragma unroll
    for (int e = 0; e < 8; e++) {
        int j = tid + e * TPB;
        float Ru = (z[e].x - sgn * zny.y) * invN;
        float Rv = (z[e].y + sgn * zny.x) * invN;
        rr[j] = __floats2half2_rn(Ru, Rv + sgn * sgnc);
    }
}

// K4: assemble output from Bt + R; 64-wide c tiles, float4 stores.
//   out[2i  ][2c..2c+1] = Bt[c][i]   out[2i+1][2c..2c+1] = R[c][i]
__global__ void k4_assemble(float* __restrict__ out) {
    __shared__ __half2 tB[32][66];   // [i_loc][c_loc], +2 pad
    __shared__ __half2 tR[32][66];
    int tx = threadIdx.x, ty = threadIdx.y;    // 32 x 8
    int ib = blockIdx.x * 32;                  // i tile (32)
    int cb = blockIdx.y * 64;                  // c tile (64)
    #pragma unroll
    for (int j = 0; j < 64; j += 8) {
        int c_loc = ty + j;
        tB[tx][c_loc] = g_Bt[(size_t)(cb + c_loc) * FN + ib + tx];
        tR[tx][c_loc] = g_R [(size_t)(cb + c_loc) * FN + ib + tx];
    }
    __syncthreads();
    float4* o4 = reinterpret_cast<float4*>(out);   // row stride 2048 float4
    int cq = (cb >> 1) + tx;                       // float4 col index
    #pragma unroll
    for (int j = 0; j < 32; j += 8) {
        int i_loc = ty + j;
        size_t ig = (size_t)(ib + i_loc);
        float2 a0 = __half22float2(tB[i_loc][2 * tx]);
        float2 a1 = __half22float2(tB[i_loc][2 * tx + 1]);
        o4[(2 * ig) * 2048 + cq] = make_float4(a0.x, a0.y, a1.x, a1.y);
        float2 b0 = __half22float2(tR[i_loc][2 * tx]);
        float2 b1 = __half22float2(tR[i_loc][2 * tx + 1]);
        o4[(2 * ig + 1) * 2048 + cq] = make_float4(b0.x, b0.y, b1.x, b1.y);
    }
}

extern "C" void kernel_launch(void* const* d_in, const int* in_sizes, int n_in,
                              void* d_out, int out_size) {
    const float* x = (const float*)d_in[0];
    float* out = (float*)d_out;
    (void)in_sizes; (void)n_in; (void)out_size;

    cudaFuncSetAttribute(k1_rowpass, cudaFuncAttributeMaxDynamicSharedMemorySize,
                         (int)SMEM_FFT);
    cudaFuncSetAttribute(k3_colpass, cudaFuncAttributeMaxDynamicSharedMemorySize,
                         (int)SMEM_FFT);

    k0_twiddle<<<1, 512>>>();
    k1_rowpass<<<NPAIR, TPB, SMEM_FFT>>>(x);
    k_reduce<<<1, TPB>>>();
    k2_transpose<<<dim3(FN / 32, FN / 32), dim3(32, 8)>>>();
    k3_colpass<<<FN, TPB, SMEM_FFT>>>();
    k4_assemble<<<dim3(FN / 32, FN / 64), dim3(32, 8)>>>(out);
}

// round 11
// speedup vs baseline: 1.4551x; 1.0614x over previous
#include <cuda_runtime.h>
#include <cuda_fp16.h>
#include <cuda_bf16.h>

// FFT-based 2x upsample, fully-real polyphase formulation (see R2/R3/R5).
// R11 = R10 + radix-16 FFT (4096 = 16^3): 3 compute stages, only 2 shared
// exchanges per FFT (4 per S-transform vs 6) -> 33% less LDS traffic, fewer
// syncs, ~60% fewer twiddle cmuls. 256 thr x 16 pts. Swizzle
// phys = a ^ ((a>>4)&15), conflict-free on all exchange patterns.

#define FN    4096
#define TPB   256
#define NPAIR (FN / 2)
#define SMEM_FFT (2 * FN * sizeof(float2))   // 64 KB double-buffer

__device__ __align__(16) __half2 g_B [(size_t)FN * FN];  // (x, R_row)
__device__ __align__(16) __half2 g_Bt[(size_t)FN * FN];  // B transposed
__device__ __align__(16) __half2 g_R [(size_t)FN * FN];  // (Ru, Rv') per (c,i)
__device__ float g_Dpart[NPAIR];
__device__ float g_D[1];
// twA[k] = e^{-2 pi i k/4096}, twB[k] = e^{+i pi k/4096}, k < 512
__device__ __align__(16) float2 g_twA[512];
__device__ __align__(16) float2 g_twB[512];

__device__ __forceinline__ float2 cmul(float2 a, float2 b) {
    return make_float2(fmaf(a.x, b.x, -a.y * b.y), fmaf(a.x, b.y, a.y * b.x));
}

// Packed fp32 complex add/sub (R10): one f32x2 instruction each.
__device__ __forceinline__ float2 cadd(float2 a, float2 b) {
    float2 r;
    asm("{\n\t.reg .b64 ra, rb, rc;\n\t"
        "mov.b64 ra, {%2, %3};\n\t"
        "mov.b64 rb, {%4, %5};\n\t"
        "add.rn.f32x2 rc, ra, rb;\n\t"
        "mov.b64 {%0, %1}, rc;\n\t}"
        : "=f"(r.x), "=f"(r.y)
        : "f"(a.x), "f"(a.y), "f"(b.x), "f"(b.y));
    return r;
}
__device__ __forceinline__ float2 csub(float2 a, float2 b) {
    float2 r;
    asm("{\n\t.reg .b64 ra, rb, rc;\n\t"
        "mov.b64 ra, {%2, %3};\n\t"
        "mov.b64 rb, {%4, %5};\n\t"
        "sub.rn.f32x2 rc, ra, rb;\n\t"
        "mov.b64 {%0, %1}, rc;\n\t}"
        : "=f"(r.x), "=f"(r.y)
        : "f"(a.x), "f"(a.y), "f"(b.x), "f"(b.y));
    return r;
}

__global__ void k0_twiddle() {
    int k = threadIdx.x;   // launched with 512
    float sn, cs;
    sincospif(-(float)k / 2048.0f, &sn, &cs);
    g_twA[k] = make_float2(cs, sn);
    sincospif((float)k / 4096.0f, &sn, &cs);
    g_twB[k] = make_float2(cs, sn);
}

// 16-point DFT as 4x4 radix-4. FWD: W16 = e^{-2pi i/16}; INV: conjugate.
template <bool INV>
__device__ __forceinline__ void bfly16(const float2 x[16], float2 y[16]) {
    float2 v[16];
    #pragma unroll
    for (int j0 = 0; j0 < 4; j0++) {
        float2 p0 = x[j0], p1 = x[j0 + 4], p2 = x[j0 + 8], p3 = x[j0 + 12];
        float2 s02 = cadd(p0, p2), d02 = csub(p0, p2);
        float2 s13 = cadd(p1, p3), d13 = csub(p1, p3);
        float2 id13 = INV ? make_float2(-d13.y, d13.x) : make_float2(d13.y, -d13.x);
        v[4 * j0 + 0] = cadd(s02, s13);
        v[4 * j0 + 1] = cadd(d02, id13);
        v[4 * j0 + 2] = csub(s02, s13);
        v[4 * j0 + 3] = csub(d02, id13);
    }
    // inner twiddles: v[4*j0 + a0] *= W16^{j0*a0}
    const float C1 = 0.92387953251128675613f, S1 = 0.38268343236508977173f;
    const float C2 = 0.70710678118654752440f;
    const float sg = INV ? 1.0f : -1.0f;
    const float2 W1 = make_float2(C1, sg * S1);
    const float2 W2 = make_float2(C2, sg * C2);
    const float2 W3 = make_float2(S1, sg * C1);
    const float2 W6 = make_float2(-C2, sg * C2);
    const float2 W9 = make_float2(-C1, -sg * S1);
    v[5]  = cmul(v[5],  W1);
    v[6]  = cmul(v[6],  W2);
    v[7]  = cmul(v[7],  W3);
    v[9]  = cmul(v[9],  W2);
    v[10] = INV ? make_float2(-v[10].y, v[10].x) : make_float2(v[10].y, -v[10].x);
    v[11] = cmul(v[11], W6);
    v[13] = cmul(v[13], W3);
    v[14] = cmul(v[14], W6);
    v[15] = cmul(v[15], W9);
    #pragma unroll
    for (int a0 = 0; a0 < 4; a0++) {
        float2 p0 = v[a0], p1 = v[4 + a0], p2 = v[8 + a0], p3 = v[12 + a0];
        float2 s02 = cadd(p0, p2), d02 = csub(p0, p2);
        float2 s13 = cadd(p1, p3), d13 = csub(p1, p3);
        float2 id13 = INV ? make_float2(-d13.y, d13.x) : make_float2(d13.y, -d13.x);
        y[a0]      = cadd(s02, s13);
        y[a0 + 4]  = cadd(d02, id13);
        y[a0 + 8]  = csub(s02, s13);
        y[a0 + 12] = csub(d02, id13);
    }
}

// y[k] *= w^k (k=1..15), w = base (conjugated for INV). Powers w^1..w^8 built
// once (7 cmuls), then shifted by w^8 for k=9..15.
template <bool INV>
__device__ __forceinline__ void twapply16(float2 y[16], float2 wb) {
    float2 w1 = INV ? make_float2(wb.x, -wb.y) : wb;
    float2 w2 = cmul(w1, w1);
    float2 w3 = cmul(w2, w1);
    float2 w4 = cmul(w2, w2);
    float2 w5 = cmul(w4, w1);
    float2 w6 = cmul(w4, w2);
    float2 w7 = cmul(w4, w3);
    float2 w8 = cmul(w4, w4);
    y[1] = cmul(y[1], w1); y[2] = cmul(y[2], w2); y[3] = cmul(y[3], w3);
    y[4] = cmul(y[4], w4); y[5] = cmul(y[5], w5); y[6] = cmul(y[6], w6);
    y[7] = cmul(y[7], w7); y[8] = cmul(y[8], w8);
    w1 = cmul(w1, w8); w2 = cmul(w2, w8); w3 = cmul(w3, w8);
    w4 = cmul(w4, w8); w5 = cmul(w5, w8); w6 = cmul(w6, w8); w7 = cmul(w7, w8);
    y[9]  = cmul(y[9],  w1); y[10] = cmul(y[10], w2); y[11] = cmul(y[11], w3);
    y[12] = cmul(y[12], w4); y[13] = cmul(y[13], w5); y[14] = cmul(y[14], w6);
    y[15] = cmul(y[15], w7);
}

// S-transform: z[j] (= data[t + 256 j]) -> N * IDFT( DFT(.) * halfshift_w ),
// zny_out <- DFT[2048]. Radix-16 DIF, 4 exchanges, swizzle a^((a>>4)&15).
__device__ __forceinline__ void stransform16(float2 z[16], float2* buf0, float2* buf1,
                                             float2* s_zny, int t, float2* zny_out) {
    const int a0  = t >> 4;
    const int s4  = t & 15;
    const int m16 = a0 + 16 * s4;
    const int tSW = 16 * a0 + (s4 ^ a0);     // phys low bits of slot "+t"

    float2 y[16];
    const float2 w1b = __ldg(&g_twA[t]);        // e^{-2pi i t/4096}
    const float2 w2b = __ldg(&g_twA[16 * s4]);  // e^{-2pi i s4/256}
    const float2 wm  = __ldg(&g_twB[m16]);      // e^{+i pi m16/4096}

    // ---- forward FFT ----
    bfly16<false>(z, y);                        // over j (stride 256) -> digit a
    twapply16<false>(y, w1b);                   // W_4096^{t a}
    #pragma unroll
    for (int a = 0; a < 16; a++) buf0[256 * a + tSW] = y[a];
    __syncthreads();
    #pragma unroll
    for (int q = 0; q < 16; q++) z[q] = buf0[256 * a0 + 16 * q + (s4 ^ q)];

    bfly16<false>(z, y);                        // over rhi -> digit b
    twapply16<false>(y, w2b);                   // W_256^{s4 b}
    #pragma unroll
    for (int b = 0; b < 16; b++) buf1[256 * a0 + 16 * b + (s4 ^ b)] = y[b];
    __syncthreads();
    #pragma unroll
    for (int q = 0; q < 16; q++) z[q] = buf1[16 * t + (q ^ s4)];

    bfly16<false>(z, y);                        // over rlo -> y[c] = X[m16+256c]
    if (t == 0) *s_zny = y[8];                  // X[2048]

    // ---- half-sample-shift phase ----
    {
        const float2 EJ[16] = {
            { 1.0f, 0.0f},
            { 0.98078528040323044913f,  0.19509032201612826785f},
            { 0.92387953251128675613f,  0.38268343236508977173f},
            { 0.83146961230254523708f,  0.55557023301960222474f},
            { 0.70710678118654752440f,  0.70710678118654752440f},
            { 0.55557023301960222474f,  0.83146961230254523708f},
            { 0.38268343236508977173f,  0.92387953251128675613f},
            { 0.19509032201612826785f,  0.98078528040323044913f},
            { 0.0f, -1.0f},
            { 0.19509032201612826785f, -0.98078528040323044913f},
            { 0.38268343236508977173f, -0.92387953251128675613f},
            { 0.55557023301960222474f, -0.83146961230254523708f},
            { 0.70710678118654752440f, -0.70710678118654752440f},
            { 0.83146961230254523708f, -0.55557023301960222474f},
            { 0.92387953251128675613f, -0.38268343236508977173f},
            { 0.98078528040323044913f, -0.19509032201612826785f}};
        #pragma unroll
        for (int c = 0; c < 16; c++) y[c] = cmul(y[c], cmul(wm, EJ[c]));
    }

    // ---- inverse FFT (exact mirror) ----
    bfly16<true>(y, z);                         // over c
    #pragma unroll
    for (int q = 0; q < 16; q++) buf0[16 * t + (q ^ s4)] = z[q];
    __syncthreads();
    #pragma unroll
    for (int q = 0; q < 16; q++) z[q] = buf0[256 * a0 + 16 * q + (s4 ^ q)];

    twapply16<true>(z, w2b);
    bfly16<true>(z, y);                         // over b -> rhi digit j
    #pragma unroll
    for (int j = 0; j < 16; j++) buf1[256 * a0 + 16 * j + (s4 ^ j)] = y[j];
    __syncthreads();
    #pragma unroll
    for (int q = 0; q < 16; q++) y[q] = buf1[256 * q + tSW];

    twapply16<true>(y, w1b);
    bfly16<true>(y, z);                         // over a -> z[j] = N*S[t + 256 j]

    *zny_out = *s_zny;                          // >= 2 syncs after the write
}

// K1: 2-for-1 row pass (block r handles input rows 2r, 2r+1).
__global__ __launch_bounds__(TPB, 2) void k1_rowpass(const float* __restrict__ x) {
    extern __shared__ float2 dsm[];
    __shared__ float2 s_zny;
    float2* buf0 = dsm;
    float2* buf1 = dsm + FN;
    int tid = threadIdx.x;
    size_t r = blockIdx.x;
    const float* u = x + (2 * r) * (size_t)FN;
    const float* v = u + FN;
    float2 z[16], z0[16];
    #pragma unroll
    for (int e = 0; e < 16; e++) {
        int j = tid + e * TPB;
        z[e] = make_float2(u[j], v[j]);
        z0[e] = z[e];
    }
    float2 zny;
    stransform16(z, buf0, buf1, &s_zny, tid, &zny);
    if (tid == 0) g_Dpart[r] = zny.x - zny.y;

    const float invN = 1.0f / 4096.0f;
    float sgn = (tid & 1) ? -1.0f : 1.0f;       // (-1)^j
    __half2* row0 = g_B + (2 * r) * (size_t)FN;
    __half2* row1 = row0 + FN;
    #pragma unroll
    for (int e = 0; e < 16; e++) {
        int j = tid + e * TPB;
        float Ru = (z[e].x - sgn * zny.y) * invN;
        float Rv = (z[e].y + sgn * zny.x) * invN;
        row0[j] = __floats2half2_rn(z0[e].x, Ru);
        row1[j] = __floats2half2_rn(z0[e].y, Rv);
    }
}

// Deterministic reduction of g_Dpart -> g_D.
__global__ void k_reduce() {
    __shared__ float sh[512];
    float s = 0.0f;
    for (int i = threadIdx.x; i < NPAIR; i += 512) s += g_Dpart[i];
    sh[threadIdx.x] = s;
    __syncthreads();
    for (int o = 256; o > 0; o >>= 1) {
        if (threadIdx.x < o) sh[threadIdx.x] += sh[threadIdx.x + o];
        __syncthreads();
    }
    if (threadIdx.x == 0) g_D[0] = sh[0];
}

// K2: transpose B [4096x4096 half2] -> Bt.
__global__ void k2_transpose() {
    __shared__ __half2 tile[32][33];
    int tx = threadIdx.x, ty = threadIdx.y;
    int cx = blockIdx.x * 32 + tx;
    int ry = blockIdx.y * 32 + ty;
    #pragma unroll
    for (int j = 0; j < 32; j += 8)
        tile[ty + j][tx] = g_B[(size_t)(ry + j) * FN + cx];
    __syncthreads();
    int ox = blockIdx.y * 32 + tx;
    int oy = blockIdx.x * 32 + ty;
    #pragma unroll
    for (int j = 0; j < 32; j += 8)
        g_Bt[(size_t)(oy + j) * FN + ox] = tile[tx][ty + j];
}

// K3: 2-for-1 column pass (block c handles output columns 2c, 2c+1).
// Writes ONLY the odd-row values: R[c][i] = (Ru, Rv + parity corr).
__global__ __launch_bounds__(TPB, 2) void k3_colpass() {
    extern __shared__ float2 dsm[];
    __shared__ float2 s_zny;
    float2* buf0 = dsm;
    float2* buf1 = dsm + FN;
    int tid = threadIdx.x;
    size_t c = blockIdx.x;
    const __half2* bt = g_Bt + c * (size_t)FN;
    float2 z[16];
    #pragma unroll
    for (int e = 0; e < 16; e++) {
        int j = tid + e * TPB;
        z[e] = __half22float2(bt[j]);
    }
    float2 zny;
    stransform16(z, buf0, buf1, &s_zny, tid, &zny);

    const float invN = 1.0f / 4096.0f;
    float corr = -g_D[0] * invN * invN;         // -D/N^2
    float sgnc = (c & 1) ? -corr : corr;        // (-1)^c * corr
    float sgn = (tid & 1) ? -1.0f : 1.0f;       // (-1)^i
    __half2* rr = g_R + c * (size_t)FN;
    #pragma unroll
    for (int e = 0; e < 16; e++) {
        int j = tid + e * TPB;
        float Ru = (z[e].x - sgn * zny.y) * invN;
        float Rv = (z[e].y + sgn * zny.x) * invN;
        rr[j] = __floats2half2_rn(Ru, Rv + sgn * sgnc);
    }
}

// K4: assemble output from Bt + R; 64-wide c tiles, float4 stores.
//   out[2i  ][2c..2c+1] = Bt[c][i]   out[2i+1][2c..2c+1] = R[c][i]
__global__ void k4_assemble(float* __restrict__ out) {
    __shared__ __half2 tB[32][66];   // [i_loc][c_loc], +2 pad
    __shared__ __half2 tR[32][66];
    int tx = threadIdx.x, ty = threadIdx.y;    // 32 x 8
    int ib = blockIdx.x * 32;                  // i tile (32)
    int cb = blockIdx.y * 64;                  // c tile (64)
    #pragma unroll
    for (int j = 0; j < 64; j += 8) {
        int c_loc = ty + j;
        tB[tx][c_loc] = g_Bt[(size_t)(cb + c_loc) * FN + ib + tx];
        tR[tx][c_loc] = g_R [(size_t)(cb + c_loc) * FN + ib + tx];
    }
    __syncthreads();
    float4* o4 = reinterpret_cast<float4*>(out);   // row stride 2048 float4
    int cq = (cb >> 1) + tx;                       // float4 col index
    #pragma unroll
    for (int j = 0; j < 32; j += 8) {
        int i_loc = ty + j;
        size_t ig = (size_t)(ib + i_loc);
        float2 a0 = __half22float2(tB[i_loc][2 * tx]);
        float2 a1 = __half22float2(tB[i_loc][2 * tx + 1]);
        o4[(2 * ig) * 2048 + cq] = make_float4(a0.x, a0.y, a1.x, a1.y);
        float2 b0 = __half22float2(tR[i_loc][2 * tx]);
        float2 b1 = __half22float2(tR[i_loc][2 * tx + 1]);
        o4[(2 * ig + 1) * 2048 + cq] = make_float4(b0.x, b0.y, b1.x, b1.y);
    }
}

extern "C" void kernel_launch(void* const* d_in, const int* in_sizes, int n_in,
                              void* d_out, int out_size) {
    const float* x = (const float*)d_in[0];
    float* out = (float*)d_out;
    (void)in_sizes; (void)n_in; (void)out_size;

    cudaFuncSetAttribute(k1_rowpass, cudaFuncAttributeMaxDynamicSharedMemorySize,
                         (int)SMEM_FFT);
    cudaFuncSetAttribute(k3_colpass, cudaFuncAttributeMaxDynamicSharedMemorySize,
                         (int)SMEM_FFT);

    k0_twiddle<<<1, 512>>>();
    k1_rowpass<<<NPAIR, TPB, SMEM_FFT>>>(x);
    k_reduce<<<1, 512>>>();
    k2_transpose<<<dim3(FN / 32, FN / 32), dim3(32, 8)>>>();
    k3_colpass<<<FN, TPB, SMEM_FFT>>>();
    k4_assemble<<<dim3(FN / 32, FN / 64), dim3(32, 8)>>>(out);
}

// round 12
// speedup vs baseline: 1.8846x; 1.2952x over previous
#include <cuda_runtime.h>
#include <cuda_fp16.h>
#include <cuda_bf16.h>

// FFT-based 2x upsample, fully-real polyphase formulation (see R2/R3/R5).
// R12: pass order reversed (columns first, rows last). The final row pass
// writes contiguous output rows -> the K4 assemble kernel is GONE; its 384MB
// of traffic collapses into F2's coalesced epilogue stores. Pipeline traffic
// 768MB -> 576MB. FFT core (radix-16, f32x2 butterflies) unchanged from R11.
//
// Pipeline: T1 (x -> xp[jp][i] half2)  F1 (col pass, 2048 blocks -> M1T)
//           reduce(D)  T2 (M1T -> M1)  F2 (row pass, 4096 blocks -> out).

#define FN    4096
#define TPB   256
#define NPAIR (FN / 2)
#define SMEM_FFT (2 * FN * sizeof(float2))   // 64 KB double-buffer

__device__ __align__(16) __half2 g_xp [(size_t)NPAIR * FN];  // [jp][i] (x even, x odd col)
__device__ __align__(16) __half2 g_M1T[(size_t)NPAIR * FN];  // [jp][i] (R even, R odd col)
__device__ __align__(16) __half2 g_M1 [(size_t)FN * NPAIR];  // [i][jp]
__device__ float g_Dpart[NPAIR];
__device__ float g_D[1];
// twA[k] = e^{-2 pi i k/4096}, twB[k] = e^{+i pi k/4096}, k < 512
__device__ __align__(16) float2 g_twA[512];
__device__ __align__(16) float2 g_twB[512];

__device__ __forceinline__ float2 cmul(float2 a, float2 b) {
    return make_float2(fmaf(a.x, b.x, -a.y * b.y), fmaf(a.x, b.y, a.y * b.x));
}

// Packed fp32 complex add/sub (R10): one f32x2 instruction each.
__device__ __forceinline__ float2 cadd(float2 a, float2 b) {
    float2 r;
    asm("{\n\t.reg .b64 ra, rb, rc;\n\t"
        "mov.b64 ra, {%2, %3};\n\t"
        "mov.b64 rb, {%4, %5};\n\t"
        "add.rn.f32x2 rc, ra, rb;\n\t"
        "mov.b64 {%0, %1}, rc;\n\t}"
        : "=f"(r.x), "=f"(r.y)
        : "f"(a.x), "f"(a.y), "f"(b.x), "f"(b.y));
    return r;
}
__device__ __forceinline__ float2 csub(float2 a, float2 b) {
    float2 r;
    asm("{\n\t.reg .b64 ra, rb, rc;\n\t"
        "mov.b64 ra, {%2, %3};\n\t"
        "mov.b64 rb, {%4, %5};\n\t"
        "sub.rn.f32x2 rc, ra, rb;\n\t"
        "mov.b64 {%0, %1}, rc;\n\t}"
        : "=f"(r.x), "=f"(r.y)
        : "f"(a.x), "f"(a.y), "f"(b.x), "f"(b.y));
    return r;
}

__global__ void k0_twiddle() {
    int k = threadIdx.x;   // launched with 512
    float sn, cs;
    sincospif(-(float)k / 2048.0f, &sn, &cs);
    g_twA[k] = make_float2(cs, sn);
    sincospif((float)k / 4096.0f, &sn, &cs);
    g_twB[k] = make_float2(cs, sn);
}

// 16-point DFT as 4x4 radix-4 (see R11). FWD: W16 = e^{-2pi i/16}; INV: conj.
template <bool INV>
__device__ __forceinline__ void bfly16(const float2 x[16], float2 y[16]) {
    float2 v[16];
    #pragma unroll
    for (int j0 = 0; j0 < 4; j0++) {
        float2 p0 = x[j0], p1 = x[j0 + 4], p2 = x[j0 + 8], p3 = x[j0 + 12];
        float2 s02 = cadd(p0, p2), d02 = csub(p0, p2);
        float2 s13 = cadd(p1, p3), d13 = csub(p1, p3);
        float2 id13 = INV ? make_float2(-d13.y, d13.x) : make_float2(d13.y, -d13.x);
        v[4 * j0 + 0] = cadd(s02, s13);
        v[4 * j0 + 1] = cadd(d02, id13);
        v[4 * j0 + 2] = csub(s02, s13);
        v[4 * j0 + 3] = csub(d02, id13);
    }
    const float C1 = 0.92387953251128675613f, S1 = 0.38268343236508977173f;
    const float C2 = 0.70710678118654752440f;
    const float sg = INV ? 1.0f : -1.0f;
    const float2 W1 = make_float2(C1, sg * S1);
    const float2 W2 = make_float2(C2, sg * C2);
    const float2 W3 = make_float2(S1, sg * C1);
    const float2 W6 = make_float2(-C2, sg * C2);
    const float2 W9 = make_float2(-C1, -sg * S1);
    v[5]  = cmul(v[5],  W1);
    v[6]  = cmul(v[6],  W2);
    v[7]  = cmul(v[7],  W3);
    v[9]  = cmul(v[9],  W2);
    v[10] = INV ? make_float2(-v[10].y, v[10].x) : make_float2(v[10].y, -v[10].x);
    v[11] = cmul(v[11], W6);
    v[13] = cmul(v[13], W3);
    v[14] = cmul(v[14], W6);
    v[15] = cmul(v[15], W9);
    #pragma unroll
    for (int a0 = 0; a0 < 4; a0++) {
        float2 p0 = v[a0], p1 = v[4 + a0], p2 = v[8 + a0], p3 = v[12 + a0];
        float2 s02 = cadd(p0, p2), d02 = csub(p0, p2);
        float2 s13 = cadd(p1, p3), d13 = csub(p1, p3);
        float2 id13 = INV ? make_float2(-d13.y, d13.x) : make_float2(d13.y, -d13.x);
        y[a0]      = cadd(s02, s13);
        y[a0 + 4]  = cadd(d02, id13);
        y[a0 + 8]  = csub(s02, s13);
        y[a0 + 12] = csub(d02, id13);
    }
}

// y[k] *= w^k (k=1..15), w = base (conjugated for INV).
template <bool INV>
__device__ __forceinline__ void twapply16(float2 y[16], float2 wb) {
    float2 w1 = INV ? make_float2(wb.x, -wb.y) : wb;
    float2 w2 = cmul(w1, w1);
    float2 w3 = cmul(w2, w1);
    float2 w4 = cmul(w2, w2);
    float2 w5 = cmul(w4, w1);
    float2 w6 = cmul(w4, w2);
    float2 w7 = cmul(w4, w3);
    float2 w8 = cmul(w4, w4);
    y[1] = cmul(y[1], w1); y[2] = cmul(y[2], w2); y[3] = cmul(y[3], w3);
    y[4] = cmul(y[4], w4); y[5] = cmul(y[5], w5); y[6] = cmul(y[6], w6);
    y[7] = cmul(y[7], w7); y[8] = cmul(y[8], w8);
    w1 = cmul(w1, w8); w2 = cmul(w2, w8); w3 = cmul(w3, w8);
    w4 = cmul(w4, w8); w5 = cmul(w5, w8); w6 = cmul(w6, w8); w7 = cmul(w7, w8);
    y[9]  = cmul(y[9],  w1); y[10] = cmul(y[10], w2); y[11] = cmul(y[11], w3);
    y[12] = cmul(y[12], w4); y[13] = cmul(y[13], w5); y[14] = cmul(y[14], w6);
    y[15] = cmul(y[15], w7);
}

// S-transform (R11, unchanged): z[j] (= data[t + 256 j]) ->
// N * IDFT( DFT(.) * halfshift_w ), zny_out <- DFT[2048].
__device__ __forceinline__ void stransform16(float2 z[16], float2* buf0, float2* buf1,
                                             float2* s_zny, int t, float2* zny_out) {
    const int a0  = t >> 4;
    const int s4  = t & 15;
    const int m16 = a0 + 16 * s4;
    const int tSW = 16 * a0 + (s4 ^ a0);

    float2 y[16];
    const float2 w1b = __ldg(&g_twA[t]);
    const float2 w2b = __ldg(&g_twA[16 * s4]);
    const float2 wm  = __ldg(&g_twB[m16]);

    // ---- forward FFT ----
    bfly16<false>(z, y);
    twapply16<false>(y, w1b);
    #pragma unroll
    for (int a = 0; a < 16; a++) buf0[256 * a + tSW] = y[a];
    __syncthreads();
    #pragma unroll
    for (int q = 0; q < 16; q++) z[q] = buf0[256 * a0 + 16 * q + (s4 ^ q)];

    bfly16<false>(z, y);
    twapply16<false>(y, w2b);
    #pragma unroll
    for (int b = 0; b < 16; b++) buf1[256 * a0 + 16 * b + (s4 ^ b)] = y[b];
    __syncthreads();
    #pragma unroll
    for (int q = 0; q < 16; q++) z[q] = buf1[16 * t + (q ^ s4)];

    bfly16<false>(z, y);
    if (t == 0) *s_zny = y[8];                  // X[2048]

    // ---- half-sample-shift phase ----
    {
        const float2 EJ[16] = {
            { 1.0f, 0.0f},
            { 0.98078528040323044913f,  0.19509032201612826785f},
            { 0.92387953251128675613f,  0.38268343236508977173f},
            { 0.83146961230254523708f,  0.55557023301960222474f},
            { 0.70710678118654752440f,  0.70710678118654752440f},
            { 0.55557023301960222474f,  0.83146961230254523708f},
            { 0.38268343236508977173f,  0.92387953251128675613f},
            { 0.19509032201612826785f,  0.98078528040323044913f},
            { 0.0f, -1.0f},
            { 0.19509032201612826785f, -0.98078528040323044913f},
            { 0.38268343236508977173f, -0.92387953251128675613f},
            { 0.55557023301960222474f, -0.83146961230254523708f},
            { 0.70710678118654752440f, -0.70710678118654752440f},
            { 0.83146961230254523708f, -0.55557023301960222474f},
            { 0.92387953251128675613f, -0.38268343236508977173f},
            { 0.98078528040323044913f, -0.19509032201612826785f}};
        #pragma unroll
        for (int c = 0; c < 16; c++) y[c] = cmul(y[c], cmul(wm, EJ[c]));
    }

    // ---- inverse FFT (exact mirror) ----
    bfly16<true>(y, z);
    #pragma unroll
    for (int q = 0; q < 16; q++) buf0[16 * t + (q ^ s4)] = z[q];
    __syncthreads();
    #pragma unroll
    for (int q = 0; q < 16; q++) z[q] = buf0[256 * a0 + 16 * q + (s4 ^ q)];

    twapply16<true>(z, w2b);
    bfly16<true>(z, y);
    #pragma unroll
    for (int j = 0; j < 16; j++) buf1[256 * a0 + 16 * j + (s4 ^ j)] = y[j];
    __syncthreads();
    #pragma unroll
    for (int q = 0; q < 16; q++) y[q] = buf1[256 * q + tSW];

    twapply16<true>(y, w1b);
    bfly16<true>(y, z);                         // z[j] = N*S[t + 256 j]

    *zny_out = *s_zny;                          // >= 2 syncs after the write
}

// T1: x (fp32, viewed as float2[4096][2048] pairing adjacent cols) ->
//     xp[jp][i] = half2(x[i][2jp], x[i][2jp+1]).
__global__ void t1_transpose(const float* __restrict__ x) {
    __shared__ float2 tile[32][33];
    const float2* xf2 = reinterpret_cast<const float2*>(x);
    int tx = threadIdx.x, ty = threadIdx.y;
    int cx = blockIdx.x * 32 + tx;      // jp
    int ry = blockIdx.y * 32 + ty;      // i
    #pragma unroll
    for (int j = 0; j < 32; j += 8)
        tile[ty + j][tx] = xf2[(size_t)(ry + j) * NPAIR + cx];
    __syncthreads();
    int ox = blockIdx.y * 32 + tx;      // i
    int oy = blockIdx.x * 32 + ty;      // jp
    #pragma unroll
    for (int j = 0; j < 32; j += 8) {
        float2 v = tile[tx][ty + j];
        g_xp[(size_t)(oy + j) * FN + ox] = __floats2half2_rn(v.x, v.y);
    }
}

// F1: column pass. Block jp transforms packed x-column pair (2jp, 2jp+1).
// Writes M1T[jp][i] = half2(R_{2jp}[i], R_{2jp+1}[i]); Dpart[jp] from Nyquist.
__global__ __launch_bounds__(TPB, 2) void f1_colpass() {
    extern __shared__ float2 dsm[];
    __shared__ float2 s_zny;
    float2* buf0 = dsm;
    float2* buf1 = dsm + FN;
    int tid = threadIdx.x;
    size_t jp = blockIdx.x;
    const __half2* xp = g_xp + jp * (size_t)FN;
    float2 z[16];
    #pragma unroll
    for (int e = 0; e < 16; e++) {
        int i = tid + e * TPB;
        z[e] = __half22float2(xp[i]);
    }
    float2 zny;
    stransform16(z, buf0, buf1, &s_zny, tid, &zny);
    if (tid == 0) g_Dpart[jp] = zny.x - zny.y;  // Dcol[2jp] - Dcol[2jp+1]

    const float invN = 1.0f / 4096.0f;
    float sgn = (tid & 1) ? -1.0f : 1.0f;       // (-1)^i
    __half2* mt = g_M1T + jp * (size_t)FN;
    #pragma unroll
    for (int e = 0; e < 16; e++) {
        int i = tid + e * TPB;
        float Ru = (z[e].x - sgn * zny.y) * invN;
        float Rv = (z[e].y + sgn * zny.x) * invN;
        mt[i] = __floats2half2_rn(Ru, Rv);
    }
}

// Deterministic reduction of g_Dpart -> g_D.
__global__ void k_reduce() {
    __shared__ float sh[512];
    float s = 0.0f;
    for (int i = threadIdx.x; i < NPAIR; i += 512) s += g_Dpart[i];
    sh[threadIdx.x] = s;
    __syncthreads();
    for (int o = 256; o > 0; o >>= 1) {
        if (threadIdx.x < o) sh[threadIdx.x] += sh[threadIdx.x + o];
        __syncthreads();
    }
    if (threadIdx.x == 0) g_D[0] = sh[0];
}

// T2: transpose M1T [2048(jp) x 4096(i) half2] -> M1 [4096(i) x 2048(jp)].
__global__ void t2_transpose() {
    __shared__ __half2 tile[32][33];
    int tx = threadIdx.x, ty = threadIdx.y;
    int cx = blockIdx.x * 32 + tx;      // i
    int ry = blockIdx.y * 32 + ty;      // jp
    #pragma unroll
    for (int j = 0; j < 32; j += 8)
        tile[ty + j][tx] = g_M1T[(size_t)(ry + j) * FN + cx];
    __syncthreads();
    int ox = blockIdx.y * 32 + tx;      // jp
    int oy = blockIdx.x * 32 + ty;      // i
    #pragma unroll
    for (int j = 0; j < 32; j += 8)
        g_M1[(size_t)(oy + j) * NPAIR + ox] = tile[tx][ty + j];
}

// F2: row pass. Block i packs (x row i fp32, M1 row i) as complex, transforms,
// and writes output rows 2i and 2i+1 directly (coalesced float2 stores).
__global__ __launch_bounds__(TPB, 2) void f2_rowpass(const float* __restrict__ x,
                                                     float* __restrict__ out) {
    extern __shared__ float2 dsm[];
    __shared__ float2 s_zny;
    float2* buf0 = dsm;
    float2* buf1 = dsm + FN;
    int tid = threadIdx.x;
    size_t i = blockIdx.x;
    const float* xr = x + i * (size_t)FN;
    const __half2* mr = g_M1 + i * (size_t)NPAIR;
    float2 z[16], z0[16];
    #pragma unroll
    for (int e = 0; e < 16; e++) {
        int j = tid + e * TPB;
        __half2 mm = mr[j >> 1];
        float mv = (j & 1) ? __high2float(mm) : __low2float(mm);
        z[e] = make_float2(xr[j], mv);
        z0[e] = z[e];
    }
    float2 zny;
    stransform16(z, buf0, buf1, &s_zny, tid, &zny);

    const float invN = 1.0f / 4096.0f;
    float corr = -g_D[0] * invN * invN;         // -D/N^2
    float sgnc = (i & 1) ? -corr : corr;        // (-1)^i * corr
    float sgn = (tid & 1) ? -1.0f : 1.0f;       // (-1)^j
    float2* o2 = reinterpret_cast<float2*>(out);
    float2* row0 = o2 + (2 * i) * (size_t)FN;       // output row 2i   (4096 float2)
    float2* row1 = o2 + (2 * i + 1) * (size_t)FN;   // output row 2i+1
    #pragma unroll
    for (int e = 0; e < 16; e++) {
        int j = tid + e * TPB;
        float Rx = (z[e].x - sgn * zny.y) * invN;
        float Rm = (z[e].y + sgn * zny.x) * invN;
        row0[j] = make_float2(z0[e].x, Rx);
        row1[j] = make_float2(z0[e].y, Rm + sgn * sgnc);
    }
}

extern "C" void kernel_launch(void* const* d_in, const int* in_sizes, int n_in,
                              void* d_out, int out_size) {
    const float* x = (const float*)d_in[0];
    float* out = (float*)d_out;
    (void)in_sizes; (void)n_in; (void)out_size;

    cudaFuncSetAttribute(f1_colpass, cudaFuncAttributeMaxDynamicSharedMemorySize,
                         (int)SMEM_FFT);
    cudaFuncSetAttribute(f2_rowpass, cudaFuncAttributeMaxDynamicSharedMemorySize,
                         (int)SMEM_FFT);

    k0_twiddle<<<1, 512>>>();
    t1_transpose<<<dim3(NPAIR / 32, FN / 32), dim3(32, 8)>>>(x);
    f1_colpass<<<NPAIR, TPB, SMEM_FFT>>>();
    k_reduce<<<1, 512>>>();
    t2_transpose<<<dim3(FN / 32, NPAIR / 32), dim3(32, 8)>>>();
    f2_rowpass<<<FN, TPB, SMEM_FFT>>>(x, out);
}

// round 13
// speedup vs baseline: 1.9588x; 1.0393x over previous
#include <cuda_runtime.h>
#include <cuda_fp16.h>
#include <cuda_bf16.h>

// FFT-based 2x upsample, fully-real polyphase formulation (see R2/R3/R5/R12).
// R13 = R12 (159.8us) with the two serialized mini-kernels fused away:
//   k0_twiddle -> T1 block(0,0) epilogue; k_reduce -> T2 block(0,0).
// 6 launches -> 4. Everything else identical to R12.
//
// Pipeline: T1 (x -> xp[jp][i] half2, + twiddle fill)
//           F1 (col pass, 2048 blocks -> M1T, Dpart)
//           T2 (M1T -> M1, + deterministic D reduction)
//           F2 (row pass, 4096 blocks -> out rows 2i/2i+1 directly).

#define FN    4096
#define TPB   256
#define NPAIR (FN / 2)
#define SMEM_FFT (2 * FN * sizeof(float2))   // 64 KB double-buffer

__device__ __align__(16) __half2 g_xp [(size_t)NPAIR * FN];  // [jp][i]
__device__ __align__(16) __half2 g_M1T[(size_t)NPAIR * FN];  // [jp][i]
__device__ __align__(16) __half2 g_M1 [(size_t)FN * NPAIR];  // [i][jp]
__device__ float g_Dpart[NPAIR];
__device__ float g_D[1];
// twA[k] = e^{-2 pi i k/4096}, twB[k] = e^{+i pi k/4096}, k < 512
__device__ __align__(16) float2 g_twA[512];
__device__ __align__(16) float2 g_twB[512];

__device__ __forceinline__ float2 cmul(float2 a, float2 b) {
    return make_float2(fmaf(a.x, b.x, -a.y * b.y), fmaf(a.x, b.y, a.y * b.x));
}

// Packed fp32 complex add/sub (R10): one f32x2 instruction each.
__device__ __forceinline__ float2 cadd(float2 a, float2 b) {
    float2 r;
    asm("{\n\t.reg .b64 ra, rb, rc;\n\t"
        "mov.b64 ra, {%2, %3};\n\t"
        "mov.b64 rb, {%4, %5};\n\t"
        "add.rn.f32x2 rc, ra, rb;\n\t"
        "mov.b64 {%0, %1}, rc;\n\t}"
        : "=f"(r.x), "=f"(r.y)
        : "f"(a.x), "f"(a.y), "f"(b.x), "f"(b.y));
    return r;
}
__device__ __forceinline__ float2 csub(float2 a, float2 b) {
    float2 r;
    asm("{\n\t.reg .b64 ra, rb, rc;\n\t"
        "mov.b64 ra, {%2, %3};\n\t"
        "mov.b64 rb, {%4, %5};\n\t"
        "sub.rn.f32x2 rc, ra, rb;\n\t"
        "mov.b64 {%0, %1}, rc;\n\t}"
        : "=f"(r.x), "=f"(r.y)
        : "f"(a.x), "f"(a.y), "f"(b.x), "f"(b.y));
    return r;
}

// 16-point DFT as 4x4 radix-4 (see R11). FWD: W16 = e^{-2pi i/16}; INV: conj.
template <bool INV>
__device__ __forceinline__ void bfly16(const float2 x[16], float2 y[16]) {
    float2 v[16];
    #pragma unroll
    for (int j0 = 0; j0 < 4; j0++) {
        float2 p0 = x[j0], p1 = x[j0 + 4], p2 = x[j0 + 8], p3 = x[j0 + 12];
        float2 s02 = cadd(p0, p2), d02 = csub(p0, p2);
        float2 s13 = cadd(p1, p3), d13 = csub(p1, p3);
        float2 id13 = INV ? make_float2(-d13.y, d13.x) : make_float2(d13.y, -d13.x);
        v[4 * j0 + 0] = cadd(s02, s13);
        v[4 * j0 + 1] = cadd(d02, id13);
        v[4 * j0 + 2] = csub(s02, s13);
        v[4 * j0 + 3] = csub(d02, id13);
    }
    const float C1 = 0.92387953251128675613f, S1 = 0.38268343236508977173f;
    const float C2 = 0.70710678118654752440f;
    const float sg = INV ? 1.0f : -1.0f;
    const float2 W1 = make_float2(C1, sg * S1);
    const float2 W2 = make_float2(C2, sg * C2);
    const float2 W3 = make_float2(S1, sg * C1);
    const float2 W6 = make_float2(-C2, sg * C2);
    const float2 W9 = make_float2(-C1, -sg * S1);
    v[5]  = cmul(v[5],  W1);
    v[6]  = cmul(v[6],  W2);
    v[7]  = cmul(v[7],  W3);
    v[9]  = cmul(v[9],  W2);
    v[10] = INV ? make_float2(-v[10].y, v[10].x) : make_float2(v[10].y, -v[10].x);
    v[11] = cmul(v[11], W6);
    v[13] = cmul(v[13], W3);
    v[14] = cmul(v[14], W6);
    v[15] = cmul(v[15], W9);
    #pragma unroll
    for (int a0 = 0; a0 < 4; a0++) {
        float2 p0 = v[a0], p1 = v[4 + a0], p2 = v[8 + a0], p3 = v[12 + a0];
        float2 s02 = cadd(p0, p2), d02 = csub(p0, p2);
        float2 s13 = cadd(p1, p3), d13 = csub(p1, p3);
        float2 id13 = INV ? make_float2(-d13.y, d13.x) : make_float2(d13.y, -d13.x);
        y[a0]      = cadd(s02, s13);
        y[a0 + 4]  = cadd(d02, id13);
        y[a0 + 8]  = csub(s02, s13);
        y[a0 + 12] = csub(d02, id13);
    }
}

// y[k] *= w^k (k=1..15), w = base (conjugated for INV).
template <bool INV>
__device__ __forceinline__ void twapply16(float2 y[16], float2 wb) {
    float2 w1 = INV ? make_float2(wb.x, -wb.y) : wb;
    float2 w2 = cmul(w1, w1);
    float2 w3 = cmul(w2, w1);
    float2 w4 = cmul(w2, w2);
    float2 w5 = cmul(w4, w1);
    float2 w6 = cmul(w4, w2);
    float2 w7 = cmul(w4, w3);
    float2 w8 = cmul(w4, w4);
    y[1] = cmul(y[1], w1); y[2] = cmul(y[2], w2); y[3] = cmul(y[3], w3);
    y[4] = cmul(y[4], w4); y[5] = cmul(y[5], w5); y[6] = cmul(y[6], w6);
    y[7] = cmul(y[7], w7); y[8] = cmul(y[8], w8);
    w1 = cmul(w1, w8); w2 = cmul(w2, w8); w3 = cmul(w3, w8);
    w4 = cmul(w4, w8); w5 = cmul(w5, w8); w6 = cmul(w6, w8); w7 = cmul(w7, w8);
    y[9]  = cmul(y[9],  w1); y[10] = cmul(y[10], w2); y[11] = cmul(y[11], w3);
    y[12] = cmul(y[12], w4); y[13] = cmul(y[13], w5); y[14] = cmul(y[14], w6);
    y[15] = cmul(y[15], w7);
}

// S-transform (R11, unchanged): z[j] (= data[t + 256 j]) ->
// N * IDFT( DFT(.) * halfshift_w ), zny_out <- DFT[2048].
__device__ __forceinline__ void stransform16(float2 z[16], float2* buf0, float2* buf1,
                                             float2* s_zny, int t, float2* zny_out) {
    const int a0  = t >> 4;
    const int s4  = t & 15;
    const int m16 = a0 + 16 * s4;
    const int tSW = 16 * a0 + (s4 ^ a0);

    float2 y[16];
    const float2 w1b = __ldg(&g_twA[t]);
    const float2 w2b = __ldg(&g_twA[16 * s4]);
    const float2 wm  = __ldg(&g_twB[m16]);

    // ---- forward FFT ----
    bfly16<false>(z, y);
    twapply16<false>(y, w1b);
    #pragma unroll
    for (int a = 0; a < 16; a++) buf0[256 * a + tSW] = y[a];
    __syncthreads();
    #pragma unroll
    for (int q = 0; q < 16; q++) z[q] = buf0[256 * a0 + 16 * q + (s4 ^ q)];

    bfly16<false>(z, y);
    twapply16<false>(y, w2b);
    #pragma unroll
    for (int b = 0; b < 16; b++) buf1[256 * a0 + 16 * b + (s4 ^ b)] = y[b];
    __syncthreads();
    #pragma unroll
    for (int q = 0; q < 16; q++) z[q] = buf1[16 * t + (q ^ s4)];

    bfly16<false>(z, y);
    if (t == 0) *s_zny = y[8];                  // X[2048]

    // ---- half-sample-shift phase ----
    {
        const float2 EJ[16] = {
            { 1.0f, 0.0f},
            { 0.98078528040323044913f,  0.19509032201612826785f},
            { 0.92387953251128675613f,  0.38268343236508977173f},
            { 0.83146961230254523708f,  0.55557023301960222474f},
            { 0.70710678118654752440f,  0.70710678118654752440f},
            { 0.55557023301960222474f,  0.83146961230254523708f},
            { 0.38268343236508977173f,  0.92387953251128675613f},
            { 0.19509032201612826785f,  0.98078528040323044913f},
            { 0.0f, -1.0f},
            { 0.19509032201612826785f, -0.98078528040323044913f},
            { 0.38268343236508977173f, -0.92387953251128675613f},
            { 0.55557023301960222474f, -0.83146961230254523708f},
            { 0.70710678118654752440f, -0.70710678118654752440f},
            { 0.83146961230254523708f, -0.55557023301960222474f},
            { 0.92387953251128675613f, -0.38268343236508977173f},
            { 0.98078528040323044913f, -0.19509032201612826785f}};
        #pragma unroll
        for (int c = 0; c < 16; c++) y[c] = cmul(y[c], cmul(wm, EJ[c]));
    }

    // ---- inverse FFT (exact mirror) ----
    bfly16<true>(y, z);
    #pragma unroll
    for (int q = 0; q < 16; q++) buf0[16 * t + (q ^ s4)] = z[q];
    __syncthreads();
    #pragma unroll
    for (int q = 0; q < 16; q++) z[q] = buf0[256 * a0 + 16 * q + (s4 ^ q)];

    twapply16<true>(z, w2b);
    bfly16<true>(z, y);
    #pragma unroll
    for (int j = 0; j < 16; j++) buf1[256 * a0 + 16 * j + (s4 ^ j)] = y[j];
    __syncthreads();
    #pragma unroll
    for (int q = 0; q < 16; q++) y[q] = buf1[256 * q + tSW];

    twapply16<true>(y, w1b);
    bfly16<true>(y, z);                         // z[j] = N*S[t + 256 j]

    *zny_out = *s_zny;                          // >= 2 syncs after the write
}

// T1: x -> xp[jp][i] = half2(x[i][2jp], x[i][2jp+1]).
// Block (0,0) additionally fills the twiddle tables (read first by F1).
__global__ void t1_transpose(const float* __restrict__ x) {
    __shared__ float2 tile[32][33];
    int tx = threadIdx.x, ty = threadIdx.y;
    int lt = ty * 32 + tx;                      // 0..255
    if (blockIdx.x == 0 && blockIdx.y == 0) {
        #pragma unroll
        for (int h = 0; h < 2; h++) {
            int k = lt + 256 * h;
            float sn, cs;
            sincospif(-(float)k / 2048.0f, &sn, &cs);
            g_twA[k] = make_float2(cs, sn);
            sincospif((float)k / 4096.0f, &sn, &cs);
            g_twB[k] = make_float2(cs, sn);
        }
    }
    const float2* xf2 = reinterpret_cast<const float2*>(x);
    int cx = blockIdx.x * 32 + tx;      // jp
    int ry = blockIdx.y * 32 + ty;      // i
    #pragma unroll
    for (int j = 0; j < 32; j += 8)
        tile[ty + j][tx] = xf2[(size_t)(ry + j) * NPAIR + cx];
    __syncthreads();
    int ox = blockIdx.y * 32 + tx;      // i
    int oy = blockIdx.x * 32 + ty;      // jp
    #pragma unroll
    for (int j = 0; j < 32; j += 8) {
        float2 v = tile[tx][ty + j];
        g_xp[(size_t)(oy + j) * FN + ox] = __floats2half2_rn(v.x, v.y);
    }
}

// F1: column pass. Block jp transforms packed x-column pair (2jp, 2jp+1).
__global__ __launch_bounds__(TPB, 2) void f1_colpass() {
    extern __shared__ float2 dsm[];
    __shared__ float2 s_zny;
    float2* buf0 = dsm;
    float2* buf1 = dsm + FN;
    int tid = threadIdx.x;
    size_t jp = blockIdx.x;
    const __half2* xp = g_xp + jp * (size_t)FN;
    float2 z[16];
    #pragma unroll
    for (int e = 0; e < 16; e++) {
        int i = tid + e * TPB;
        z[e] = __half22float2(xp[i]);
    }
    float2 zny;
    stransform16(z, buf0, buf1, &s_zny, tid, &zny);
    if (tid == 0) g_Dpart[jp] = zny.x - zny.y;

    const float invN = 1.0f / 4096.0f;
    float sgn = (tid & 1) ? -1.0f : 1.0f;       // (-1)^i
    __half2* mt = g_M1T + jp * (size_t)FN;
    #pragma unroll
    for (int e = 0; e < 16; e++) {
        int i = tid + e * TPB;
        float Ru = (z[e].x - sgn * zny.y) * invN;
        float Rv = (z[e].y + sgn * zny.x) * invN;
        mt[i] = __floats2half2_rn(Ru, Rv);
    }
}

// T2: transpose M1T -> M1. Block (0,0) additionally reduces Dpart -> D
// (deterministic: fixed stride order + smem tree). F2 reads g_D next kernel.
__global__ void t2_transpose() {
    __shared__ __half2 tile[32][33];
    __shared__ float sh[256];
    int tx = threadIdx.x, ty = threadIdx.y;
    int lt = ty * 32 + tx;                      // 0..255
    if (blockIdx.x == 0 && blockIdx.y == 0) {
        float s = 0.0f;
        #pragma unroll
        for (int h = 0; h < 8; h++) s += g_Dpart[lt + 256 * h];
        sh[lt] = s;
        __syncthreads();
        for (int o = 128; o > 0; o >>= 1) {
            if (lt < o) sh[lt] += sh[lt + o];
            __syncthreads();
        }
        if (lt == 0) g_D[0] = sh[0];
    }
    int cx = blockIdx.x * 32 + tx;      // i
    int ry = blockIdx.y * 32 + ty;      // jp
    #pragma unroll
    for (int j = 0; j < 32; j += 8)
        tile[ty + j][tx] = g_M1T[(size_t)(ry + j) * FN + cx];
    __syncthreads();
    int ox = blockIdx.y * 32 + tx;      // jp
    int oy = blockIdx.x * 32 + ty;      // i
    #pragma unroll
    for (int j = 0; j < 32; j += 8)
        g_M1[(size_t)(oy + j) * NPAIR + ox] = tile[tx][ty + j];
}

// F2: row pass. Block i packs (x row i fp32, M1 row i) as complex, transforms,
// writes output rows 2i and 2i+1 directly (coalesced float2 stores).
__global__ __launch_bounds__(TPB, 2) void f2_rowpass(const float* __restrict__ x,
                                                     float* __restrict__ out) {
    extern __shared__ float2 dsm[];
    __shared__ float2 s_zny;
    float2* buf0 = dsm;
    float2* buf1 = dsm + FN;
    int tid = threadIdx.x;
    size_t i = blockIdx.x;
    const float* xr = x + i * (size_t)FN;
    const __half2* mr = g_M1 + i * (size_t)NPAIR;
    float2 z[16], z0[16];
    #pragma unroll
    for (int e = 0; e < 16; e++) {
        int j = tid + e * TPB;
        __half2 mm = mr[j >> 1];
        float mv = (j & 1) ? __high2float(mm) : __low2float(mm);
        z[e] = make_float2(xr[j], mv);
        z0[e] = z[e];
    }
    float2 zny;
    stransform16(z, buf0, buf1, &s_zny, tid, &zny);

    const float invN = 1.0f / 4096.0f;
    float corr = -g_D[0] * invN * invN;         // -D/N^2
    float sgnc = (i & 1) ? -corr : corr;        // (-1)^i * corr
    float sgn = (tid & 1) ? -1.0f : 1.0f;       // (-1)^j
    float2* o2 = reinterpret_cast<float2*>(out);
    float2* row0 = o2 + (2 * i) * (size_t)FN;
    float2* row1 = o2 + (2 * i + 1) * (size_t)FN;
    #pragma unroll
    for (int e = 0; e < 16; e++) {
        int j = tid + e * TPB;
        float Rx = (z[e].x - sgn * zny.y) * invN;
        float Rm = (z[e].y + sgn * zny.x) * invN;
        row0[j] = make_float2(z0[e].x, Rx);
        row1[j] = make_float2(z0[e].y, Rm + sgn * sgnc);
    }
}

extern "C" void kernel_launch(void* const* d_in, const int* in_sizes, int n_in,
                              void* d_out, int out_size) {
    const float* x = (const float*)d_in[0];
    float* out = (float*)d_out;
    (void)in_sizes; (void)n_in; (void)out_size;

    cudaFuncSetAttribute(f1_colpass, cudaFuncAttributeMaxDynamicSharedMemorySize,
                         (int)SMEM_FFT);
    cudaFuncSetAttribute(f2_rowpass, cudaFuncAttributeMaxDynamicSharedMemorySize,
                         (int)SMEM_FFT);

    t1_transpose<<<dim3(NPAIR / 32, FN / 32), dim3(32, 8)>>>(x);
    f1_colpass<<<NPAIR, TPB, SMEM_FFT>>>();
    t2_transpose<<<dim3(FN / 32, NPAIR / 32), dim3(32, 8)>>>();
    f2_rowpass<<<FN, TPB, SMEM_FFT>>>(x, out);
}